// round 11
// baseline (speedup 1.0000x reference)
#include <cuda_runtime.h>

// TBSyntaxParser: B=8192, buffer [B,128,50] f32, W [3,300], b[3],
// legal [B,3], buffer_index [B] i32, stack_indexes [B,3] i32.
// out[B,3] = exp(min(X@W.T+b,10)) * legal, X = 6 gathered rows of 50 floats.
//
// Gather via cp.async.bulk (TMA engine, bypasses the per-SM L1-MSHR
// outstanding-miss cap that pinned all LDG variants at ~1.8TB/s):
// 16 producer threads per CTA issue 6x224B bulk copies each into a smem tile
// (row start aligned down to 16B; 0/8B parity = row&1 kept per state),
// one mbarrier with expect_tx = full tile. 8 compute warps x 2 states keep
// the proven packed-FFMA2 + packed-butterfly shape, reading rows from smem.

#define HH      50
#define ROWE    25
#define W1      300
#define W2      600
#define SPC     16          // states per CTA
#define THR     256         // 8 warps, 2 states/warp
#define CTAS    512         // 512*16 = 8192
#define SLOT64  28          // 224B per row slot, in u64
#define TILE_B  (SPC * 6 * 224)   // 21504 bytes

typedef unsigned long long u64;

__device__ __forceinline__ void ffma2(u64& acc, u64 x, u64 w) {
    asm("fma.rn.f32x2 %0, %1, %2, %3;" : "=l"(acc) : "l"(x), "l"(w), "l"(acc));
}
__device__ __forceinline__ u64 fadd2(u64 a, u64 b) {
    u64 r;
    asm("add.rn.f32x2 %0, %1, %2;" : "=l"(r) : "l"(a), "l"(b));
    return r;
}
__device__ __forceinline__ float fold2(u64 a) {
    float lo, hi;
    asm("mov.b64 {%0,%1}, %2;" : "=f"(lo), "=f"(hi) : "l"(a));
    return lo + hi;
}
__device__ __forceinline__ u64 pack2(float lo, float hi) {
    u64 r;
    asm("mov.b64 %0, {%1,%2};" : "=l"(r) : "f"(lo), "f"(hi));
    return r;
}
__device__ __forceinline__ u64 shfl_xor64(u64 v, int off) {
    unsigned lo = (unsigned)v, hi = (unsigned)(v >> 32);
    lo = __shfl_xor_sync(0xffffffffu, lo, off);
    hi = __shfl_xor_sync(0xffffffffu, hi, off);
    return ((u64)hi << 32) | lo;
}
__device__ __forceinline__ unsigned smem_u32(const void* p) {
    unsigned a;
    asm("{ .reg .u64 t; cvta.to.shared.u64 t, %1; cvt.u32.u64 %0, t; }"
        : "=r"(a) : "l"(p));
    return a;
}
__device__ __forceinline__ void bulk_cp(unsigned dst, const void* src,
                                        unsigned bytes, unsigned mbar) {
    asm volatile(
        "cp.async.bulk.shared::cluster.global.mbarrier::complete_tx::bytes "
        "[%0], [%1], %2, [%3];"
        :: "r"(dst), "l"(src), "r"(bytes), "r"(mbar) : "memory");
}

__global__ __launch_bounds__(THR)
void tb_parser_kernel(const float* __restrict__ buffer,
                      const float* __restrict__ W,
                      const float* __restrict__ bvec,
                      const float* __restrict__ legal,
                      const int*   __restrict__ buf_idx,
                      const int*   __restrict__ stk_idx,
                      float*       __restrict__ out)
{
    __shared__ __align__(16) u64 tile[SPC * 6 * SLOT64];  // 21504 B
    __shared__ unsigned parity[SPC];                      // bit r = row_r & 1
    __shared__ __align__(8) u64 mbar_store;

    const int tid   = threadIdx.x;
    const int warp  = tid >> 5;
    const int lane  = tid & 31;
    const int sbase = blockIdx.x * SPC;

    const unsigned mbar = smem_u32(&mbar_store);
    if (tid == 0) {
        asm volatile("mbarrier.init.shared.b64 [%0], 1;" :: "r"(mbar) : "memory");
    }
    __syncthreads();

    // ---- producers: 16 threads, one state each: idx loads + 6 bulk copies ----
    if (tid < SPC) {
        const int s  = sbase + tid;
        const int bi = __ldg(buf_idx + s);
        const int r3 = __ldg(stk_idx + s * 3 + 0);
        const int r4 = __ldg(stk_idx + s * 3 + 1);
        const int r5 = __ldg(stk_idx + s * 3 + 2);
        const int rows[6] = { bi, bi + 1, bi + 2, r3, r4, r5 };

        unsigned pm = 0;
        const char* sb = (const char*)buffer + (size_t)s * (128 * HH * 4);
        #pragma unroll
        for (int k = 0; k < 6; k++) {
            const size_t byte_off = (size_t)rows[k] * (HH * 4);   // row*200
            const char*  src = sb + (byte_off & ~(size_t)15);     // align down 16
            pm |= ((unsigned)rows[k] & 1u) << k;                  // 8B offset flag
            const unsigned dst = smem_u32(&tile[(tid * 6 + k) * SLOT64]);
            bulk_cp(dst, src, 224u, mbar);
        }
        parity[tid] = pm;
        if (tid == 0) {
            asm volatile("mbarrier.arrive.expect_tx.shared.b64 _, [%0], %1;"
                         :: "r"(mbar), "r"((unsigned)TILE_B) : "memory");
        }
    }

    // ---- independent work under copy latency: W + legal/bvec ----
    const int  c  = (lane < ROWE) ? lane : (ROWE - 1);
    const bool on = (lane < ROWE);

    u64 w[6][3];
    #pragma unroll
    for (int r = 0; r < 6; r++) {
        const float* wp = W + r * HH + c * 2;
        w[r][0] = *(const u64*)(wp);
        w[r][1] = *(const u64*)(wp + W1);
        w[r][2] = *(const u64*)(wp + W2);
    }
    const int gsA = sbase + warp * 2;       // this warp's first global state
    float lg = 0.f, bb = 0.f;
    if (lane < 6) {
        lg = __ldg(legal + gsA * 3 + lane);
        bb = __ldg(bvec + (lane < 3 ? lane : lane - 3));
    }

    __syncthreads();   // drain parity STS (does NOT wait for bulk copies)

    // ---- wait for all 96 bulk copies (expect_tx = 21504B) ----
    {
        unsigned done;
        asm volatile(
            "{\n\t.reg .pred p;\n\t"
            "mbarrier.try_wait.parity.acquire.cta.shared::cta.b64 p, [%1], 0;\n\t"
            "selp.b32 %0, 1, 0, p;\n\t}"
            : "=r"(done) : "r"(mbar) : "memory");
        if (!done) {
            asm volatile(
                "{\n\t.reg .pred P1;\n\t"
                "WL_%=:\n\t"
                "mbarrier.try_wait.parity.acquire.cta.shared::cta.b64 P1, [%0], 0, 0x989680;\n\t"
                "@P1 bra.uni WD_%=;\n\t"
                "bra.uni WL_%=;\n\t"
                "WD_%=:\n\t}"
                :: "r"(mbar) : "memory");
        }
    }

    // ---- compute: 2 states per warp from smem ----
    const int slA = warp * 2;               // local states slA, slA+1
    const unsigned pmA = parity[slA];
    const unsigned pmB = parity[slA + 1];

    u64 xA[6], xB[6];
    #pragma unroll
    for (int r = 0; r < 6; r++) {
        xA[r] = tile[((slA    ) * 6 + r) * SLOT64 + ((pmA >> r) & 1u) + c];
        xB[r] = tile[((slA + 1) * 6 + r) * SLOT64 + ((pmB >> r) & 1u) + c];
    }
    if (!on) {
        #pragma unroll
        for (int r = 0; r < 6; r++) { xA[r] = 0ULL; xB[r] = 0ULL; }
    }

    u64 a0A = 0, a1A = 0, a2A = 0, a0B = 0, a1B = 0, a2B = 0;
    #pragma unroll
    for (int r = 0; r < 6; r++) {
        ffma2(a0A, xA[r], w[r][0]);  ffma2(a0B, xB[r], w[r][0]);
        ffma2(a1A, xA[r], w[r][1]);  ffma2(a1B, xB[r], w[r][1]);
        ffma2(a2A, xA[r], w[r][2]);  ffma2(a2B, xB[r], w[r][2]);
    }

    float f0A = on ? fold2(a0A) : 0.f;
    float f1A = on ? fold2(a1A) : 0.f;
    float f2A = on ? fold2(a2A) : 0.f;
    float f0B = on ? fold2(a0B) : 0.f;
    float f1B = on ? fold2(a1B) : 0.f;
    float f2B = on ? fold2(a2B) : 0.f;

    u64 pA = pack2(f0A, f1A);
    u64 pB = pack2(f0B, f1B);
    u64 p2 = pack2(f2A, f2B);
    #pragma unroll
    for (int off = 16; off; off >>= 1) {
        pA = fadd2(pA, shfl_xor64(pA, off));
        pB = fadd2(pB, shfl_xor64(pB, off));
        p2 = fadd2(p2, shfl_xor64(p2, off));
    }

    if (lane < 6) {
        float vA0, vA1, vB0, vB1, v2A, v2B;
        asm("mov.b64 {%0,%1}, %2;" : "=f"(vA0), "=f"(vA1) : "l"(pA));
        asm("mov.b64 {%0,%1}, %2;" : "=f"(vB0), "=f"(vB1) : "l"(pB));
        asm("mov.b64 {%0,%1}, %2;" : "=f"(v2A), "=f"(v2B) : "l"(p2));
        const float a = (lane == 0) ? vA0 : (lane == 1) ? vA1 : (lane == 2) ? v2A
                      : (lane == 3) ? vB0 : (lane == 4) ? vB1 : v2B;
        out[gsA * 3 + lane] = __expf(fminf(a + bb, 10.f)) * lg;
    }
}

extern "C" void kernel_launch(void* const* d_in, const int* in_sizes, int n_in,
                              void* d_out, int out_size)
{
    const float* buffer = (const float*)d_in[0];
    const float* W      = (const float*)d_in[1];
    const float* bvec   = (const float*)d_in[2];
    const float* legal  = (const float*)d_in[3];
    const int*   bufidx = (const int*)d_in[4];
    const int*   stkidx = (const int*)d_in[5];
    float* out = (float*)d_out;

    tb_parser_kernel<<<CTAS, THR>>>(buffer, W, bvec, legal, bufidx, stkidx, out);
}

// round 12
// speedup vs baseline: 1.2338x; 1.2338x over previous
#include <cuda_runtime.h>

// TBSyntaxParser: B=8192, buffer [B,128,50] f32, W [3,300], b[3],
// legal [B,3], buffer_index [B] i32, stack_indexes [B,3] i32.
// out[B,3] = exp(min(X@W.T+b,10)) * legal, X = 6 gathered rows of 50 floats.
//
// Warp-per-state, maximum occupancy (8192 warps) to hide L2/DRAM latency.
// Mature pipeline: idx loads first, smem-W staging overlaps the idx trip,
// 6 batched gather LDG.64 issued BEFORE the barrier (barrier wait overlaps
// gather latency), packed fma.rn.f32x2 vs shared W, packed shfl butterfly.

#define HH   50
#define ROWE 25
#define NP2  150          // 300 floats as 150 u64
#define THR  256          // 8 warps/CTA, 1 state/warp
#define CTAS 1024

typedef unsigned long long u64;

__device__ __forceinline__ void ffma2(u64& acc, u64 x, u64 w) {
    asm("fma.rn.f32x2 %0, %1, %2, %3;" : "=l"(acc) : "l"(x), "l"(w), "l"(acc));
}
__device__ __forceinline__ u64 fadd2(u64 a, u64 b) {
    u64 r;
    asm("add.rn.f32x2 %0, %1, %2;" : "=l"(r) : "l"(a), "l"(b));
    return r;
}
__device__ __forceinline__ float fold2(u64 a) {
    float lo, hi;
    asm("mov.b64 {%0,%1}, %2;" : "=f"(lo), "=f"(hi) : "l"(a));
    return lo + hi;
}
__device__ __forceinline__ u64 pack2(float lo, float hi) {
    u64 r;
    asm("mov.b64 %0, {%1,%2};" : "=l"(r) : "f"(lo), "f"(hi));
    return r;
}
__device__ __forceinline__ u64 shfl_xor64(u64 v, int off) {
    unsigned lo = (unsigned)v, hi = (unsigned)(v >> 32);
    lo = __shfl_xor_sync(0xffffffffu, lo, off);
    hi = __shfl_xor_sync(0xffffffffu, hi, off);
    return ((u64)hi << 32) | lo;
}

__global__ __launch_bounds__(THR)
void tb_parser_kernel(const float* __restrict__ buffer,
                      const float* __restrict__ W,
                      const float* __restrict__ bvec,
                      const float* __restrict__ legal,
                      const int*   __restrict__ buf_idx,
                      const int*   __restrict__ stk_idx,
                      float*       __restrict__ out)
{
    __shared__ u64 Ws2[3 * NP2];        // 3.6 KB

    const int tid   = threadIdx.x;
    const int warp  = tid >> 5;
    const int lane  = tid & 31;
    const int state = blockIdx.x * 8 + warp;

    // ---- dependent index loads first ----
    const int bi = __ldg(buf_idx + state);
    const int s0 = __ldg(stk_idx + state * 3 + 0);
    const int s1 = __ldg(stk_idx + state * 3 + 1);
    const int s2 = __ldg(stk_idx + state * 3 + 2);
    float lg = 0.f, bb = 0.f;
    if (lane < 3) {
        lg = __ldg(legal + state * 3 + lane);
        bb = __ldg(bvec + lane);
    }

    // ---- W staging: independent LDG+STS overlapping the idx trip ----
    const u64* Wg = (const u64*)W;
    #pragma unroll
    for (int i = tid; i < 3 * NP2; i += THR) Ws2[i] = Wg[i];

    // ---- batched gathers issued BEFORE the barrier ----
    const int  c  = (lane < ROWE) ? lane : (ROWE - 1);
    const bool on = (lane < ROWE);
    const float* base = buffer + (size_t)state * (128 * HH) + c * 2;

    u64 xv[6];
    xv[0] = *(const u64*)(base + (bi    ) * HH);
    xv[1] = *(const u64*)(base + (bi + 1) * HH);
    xv[2] = *(const u64*)(base + (bi + 2) * HH);
    xv[3] = *(const u64*)(base + (s0    ) * HH);
    xv[4] = *(const u64*)(base + (s1    ) * HH);
    xv[5] = *(const u64*)(base + (s2    ) * HH);
    if (!on) {
        #pragma unroll
        for (int r = 0; r < 6; r++) xv[r] = 0ULL;
    }

    __syncthreads();   // W visible; wait overlaps the gather round-trip

    // ---- packed dot products against shared W ----
    u64 a0 = 0, a1 = 0, a2 = 0;
    #pragma unroll
    for (int r = 0; r < 6; r++) {
        const int j = r * ROWE + c;
        ffma2(a0, xv[r], Ws2[j]);
        ffma2(a1, xv[r], Ws2[NP2 + j]);
        ffma2(a2, xv[r], Ws2[2 * NP2 + j]);
    }

    float f0 = on ? fold2(a0) : 0.f;
    float f1 = on ? fold2(a1) : 0.f;
    float f2 = on ? fold2(a2) : 0.f;

    // ---- packed butterfly: (f0,f1) as one u64 chain + f2 scalar ----
    u64 p01 = pack2(f0, f1);
    #pragma unroll
    for (int off = 16; off; off >>= 1) {
        p01 = fadd2(p01, shfl_xor64(p01, off));
        f2 += __shfl_xor_sync(0xffffffffu, f2, off);
    }

    if (lane < 3) {
        float v0, v1;
        asm("mov.b64 {%0,%1}, %2;" : "=f"(v0), "=f"(v1) : "l"(p01));
        const float a = (lane == 0) ? v0 : (lane == 1) ? v1 : f2;
        out[state * 3 + lane] = __expf(fminf(a + bb, 10.f)) * lg;
    }
}

extern "C" void kernel_launch(void* const* d_in, const int* in_sizes, int n_in,
                              void* d_out, int out_size)
{
    const float* buffer = (const float*)d_in[0];
    const float* W      = (const float*)d_in[1];
    const float* bvec   = (const float*)d_in[2];
    const float* legal  = (const float*)d_in[3];
    const int*   bufidx = (const int*)d_in[4];
    const int*   stkidx = (const int*)d_in[5];
    float* out = (float*)d_out;

    tb_parser_kernel<<<CTAS, THR>>>(buffer, W, bvec, legal, bufidx, stkidx, out);
}

// round 13
// speedup vs baseline: 1.6411x; 1.3301x over previous
#include <cuda_runtime.h>

// TBSyntaxParser: B=8192, buffer [B,128,50] f32, W [3,300], b[3],
// legal [B,3], buffer_index [B] i32, stack_indexes [B,3] i32.
// out[B,3] = exp(min(X@W.T+b,10)) * legal, X = 6 gathered rows of 50 floats.
//
// Converged design: two adjacent states per warp (instruction-count sweet
// spot for the warm-replay regime), smem-staged W (each LDS.64 feeds both
// states), int2-vectorized index loads, 6+6 batched gather LDG.64 issued
// before the W barrier (barrier wait overlaps gather latency), packed
// fma.rn.f32x2 dot products, packed f32x2 shfl butterfly, 296x448 grid
// (exactly 2 CTAs / 28 warps per SM, balanced single wave).

#define HH   50
#define ROWE 25
#define NP2  150          // 300 floats = 150 u64
#define CTAS 296
#define THR  448          // 14 warps/CTA, 2 states/warp
#define NSTATES 8192

typedef unsigned long long u64;

__device__ __forceinline__ void ffma2(u64& acc, u64 x, u64 w) {
    asm("fma.rn.f32x2 %0, %1, %2, %3;" : "=l"(acc) : "l"(x), "l"(w), "l"(acc));
}
__device__ __forceinline__ u64 fadd2(u64 a, u64 b) {
    u64 r;
    asm("add.rn.f32x2 %0, %1, %2;" : "=l"(r) : "l"(a), "l"(b));
    return r;
}
__device__ __forceinline__ float fold2(u64 a) {
    float lo, hi;
    asm("mov.b64 {%0,%1}, %2;" : "=f"(lo), "=f"(hi) : "l"(a));
    return lo + hi;
}
__device__ __forceinline__ u64 pack2(float lo, float hi) {
    u64 r;
    asm("mov.b64 %0, {%1,%2};" : "=l"(r) : "f"(lo), "f"(hi));
    return r;
}
__device__ __forceinline__ u64 shfl_xor64(u64 v, int off) {
    unsigned lo = (unsigned)v, hi = (unsigned)(v >> 32);
    lo = __shfl_xor_sync(0xffffffffu, lo, off);
    hi = __shfl_xor_sync(0xffffffffu, hi, off);
    return ((u64)hi << 32) | lo;
}

__global__ __launch_bounds__(THR, 2)
void tb_parser_kernel(const float* __restrict__ buffer,
                      const float* __restrict__ W,
                      const float* __restrict__ bvec,
                      const float* __restrict__ legal,
                      const int*   __restrict__ buf_idx,
                      const int*   __restrict__ stk_idx,
                      float*       __restrict__ out)
{
    __shared__ u64 Ws2[3 * NP2];        // 3.6 KB

    const int tid  = threadIdx.x;
    const int warp = tid >> 5;
    const int lane = tid & 31;
    const int gw   = blockIdx.x * 14 + warp;   // 0..4143
    const int sA   = gw * 2;

    // predicated, not early-return: all threads must reach __syncthreads
    const bool live = (sA < NSTATES);

    // ---- vectorized dependent index loads (4x LDG.64, 8B-aligned) ----
    int biA = 0, biB = 0, aA0 = 0, aA1 = 0, aA2 = 0, aB0 = 0, aB1 = 0, aB2 = 0;
    float lg = 0.f, bb = 0.f;
    if (live) {
        const int2 bi2 = __ldg((const int2*)(buf_idx + sA));
        const int2 s01 = __ldg((const int2*)(stk_idx + sA * 3));
        const int2 s23 = __ldg((const int2*)(stk_idx + sA * 3 + 2));
        const int2 s45 = __ldg((const int2*)(stk_idx + sA * 3 + 4));
        biA = bi2.x; biB = bi2.y;
        aA0 = s01.x; aA1 = s01.y; aA2 = s23.x;
        aB0 = s23.y; aB1 = s45.x; aB2 = s45.y;
        if (lane < 6) {
            lg = __ldg(legal + sA * 3 + lane);
            bb = __ldg(bvec + (lane < 3 ? lane : lane - 3));
        }
    }

    // ---- W staging: independent LDG+STS overlapping the idx trip ----
    const u64* Wg = (const u64*)W;
    #pragma unroll
    for (int i = tid; i < 3 * NP2; i += THR) Ws2[i] = Wg[i];

    // ---- batched gathers (12 LDG.64 in flight) BEFORE the barrier ----
    const int  c  = (lane < ROWE) ? lane : (ROWE - 1);
    const bool on = (lane < ROWE) && live;

    u64 xA[6], xB[6];
    if (live) {
        const float* baseA = buffer + (size_t)sA * (128 * HH) + c * 2;
        const float* baseB = baseA + 128 * HH;
        xA[0] = *(const u64*)(baseA + (biA    ) * HH);
        xA[1] = *(const u64*)(baseA + (biA + 1) * HH);
        xA[2] = *(const u64*)(baseA + (biA + 2) * HH);
        xA[3] = *(const u64*)(baseA + (aA0    ) * HH);
        xA[4] = *(const u64*)(baseA + (aA1    ) * HH);
        xA[5] = *(const u64*)(baseA + (aA2    ) * HH);
        xB[0] = *(const u64*)(baseB + (biB    ) * HH);
        xB[1] = *(const u64*)(baseB + (biB + 1) * HH);
        xB[2] = *(const u64*)(baseB + (biB + 2) * HH);
        xB[3] = *(const u64*)(baseB + (aB0    ) * HH);
        xB[4] = *(const u64*)(baseB + (aB1    ) * HH);
        xB[5] = *(const u64*)(baseB + (aB2    ) * HH);
    }
    if (!on) {
        #pragma unroll
        for (int r = 0; r < 6; r++) { xA[r] = 0ULL; xB[r] = 0ULL; }
    }

    __syncthreads();   // W visible; wait overlaps the gather round-trip

    // ---- packed dot products; each W LDS feeds both states ----
    u64 a0A = 0, a1A = 0, a2A = 0, a0B = 0, a1B = 0, a2B = 0;
    #pragma unroll
    for (int r = 0; r < 6; r++) {
        const int j = r * ROWE + c;
        const u64 w0 = Ws2[j];
        const u64 w1 = Ws2[NP2 + j];
        const u64 w2 = Ws2[2 * NP2 + j];
        ffma2(a0A, xA[r], w0);  ffma2(a0B, xB[r], w0);
        ffma2(a1A, xA[r], w1);  ffma2(a1B, xB[r], w1);
        ffma2(a2A, xA[r], w2);  ffma2(a2B, xB[r], w2);
    }

    float f0A = on ? fold2(a0A) : 0.f;
    float f1A = on ? fold2(a1A) : 0.f;
    float f2A = on ? fold2(a2A) : 0.f;
    float f0B = on ? fold2(a0B) : 0.f;
    float f1B = on ? fold2(a1B) : 0.f;
    float f2B = on ? fold2(a2B) : 0.f;

    // ---- packed butterfly reduction: 3 chains for 6 partials ----
    u64 pA = pack2(f0A, f1A);
    u64 pB = pack2(f0B, f1B);
    u64 p2 = pack2(f2A, f2B);
    #pragma unroll
    for (int off = 16; off; off >>= 1) {
        pA = fadd2(pA, shfl_xor64(pA, off));
        pB = fadd2(pB, shfl_xor64(pB, off));
        p2 = fadd2(p2, shfl_xor64(p2, off));
    }

    if (live && lane < 6) {
        float vA0, vA1, vB0, vB1, v2A, v2B;
        asm("mov.b64 {%0,%1}, %2;" : "=f"(vA0), "=f"(vA1) : "l"(pA));
        asm("mov.b64 {%0,%1}, %2;" : "=f"(vB0), "=f"(vB1) : "l"(pB));
        asm("mov.b64 {%0,%1}, %2;" : "=f"(v2A), "=f"(v2B) : "l"(p2));
        const float a = (lane == 0) ? vA0 : (lane == 1) ? vA1 : (lane == 2) ? v2A
                      : (lane == 3) ? vB0 : (lane == 4) ? vB1 : v2B;
        out[sA * 3 + lane] = __expf(fminf(a + bb, 10.f)) * lg;
    }
}

extern "C" void kernel_launch(void* const* d_in, const int* in_sizes, int n_in,
                              void* d_out, int out_size)
{
    const float* buffer = (const float*)d_in[0];
    const float* W      = (const float*)d_in[1];
    const float* bvec   = (const float*)d_in[2];
    const float* legal  = (const float*)d_in[3];
    const int*   bufidx = (const int*)d_in[4];
    const int*   stkidx = (const int*)d_in[5];
    float* out = (float*)d_out;

    tb_parser_kernel<<<CTAS, THR>>>(buffer, W, bvec, legal, bufidx, stkidx, out);
}